// round 3
// baseline (speedup 1.0000x reference)
#include <cuda_runtime.h>

#define NB 2
#define NE 10
#define NC 64
#define NH 128
#define NW 256
#define HW (NH*NW)
#define TW 32

// Persistent device scratch (no allocations allowed).
__device__ float d_Mt[NC*NC];          // Mt[cp*64+c] = M[c][cp] = sum_d Wq[d,c]*Wk[d,cp]
__device__ float d_Pt[NC*NC];          // Pt[c*64+d]  = P[d][c]  = sum_e Wo[d,e]*Wv[e,c]
__device__ float d_s3[NB*NH*NE*NE];    // axis=3 scores->weights [b][h][i][j]
__device__ float d_s4[NB*NW*NE*NE];    // axis=4 scores->weights [b][w][i][j]

typedef unsigned long long u64;

__device__ __forceinline__ u64 pack2(float lo, float hi){
    u64 r; asm("mov.b64 %0, {%1, %2};" : "=l"(r) : "f"(lo), "f"(hi)); return r;
}
__device__ __forceinline__ void fma2(u64 &d, u64 a, u64 b){
    asm("fma.rn.f32x2 %0, %1, %2, %0;" : "+l"(d) : "l"(a), "l"(b));
}
__device__ __forceinline__ float2 unpack2(u64 v){
    float2 r; asm("mov.b64 {%0, %1}, %2;" : "=f"(r.x), "=f"(r.y) : "l"(v)); return r;
}

// ---------------- prep: M = Wq^T Wk, P = Wo Wv (both stored transposed) ----------------
__global__ void prep_kernel(const float* __restrict__ Wq, const float* __restrict__ Wk,
                            const float* __restrict__ Wv, const float* __restrict__ Wo){
    int idx = blockIdx.x * blockDim.x + threadIdx.x;
    if (idx < NC*NC){
        int cp = idx >> 6, c = idx & 63;
        float s = 0.f;
        #pragma unroll 8
        for (int d = 0; d < NC; d++) s += Wq[d*NC + c] * Wk[d*NC + cp];
        d_Mt[idx] = s;                               // Mt[cp][c]
    } else if (idx < 2*NC*NC){
        int t = idx - NC*NC;
        int c = t >> 6, d = t & 63;
        float s = 0.f;
        #pragma unroll 8
        for (int e = 0; e < NC; e++) s += Wo[d*NC + e] * Wv[e*NC + c];
        d_Pt[t] = s;                                 // Pt[c][d]
    }
}

// ---------------- zero score accumulators ----------------
__global__ void zero_kernel(){
    int i = blockIdx.x * blockDim.x + threadIdx.x;
    if (i < NB*NH*NE*NE) d_s3[i] = 0.f;
    else {
        int r = i - NB*NH*NE*NE;
        if (r < NB*NW*NE*NE) d_s4[r] = 0.f;
    }
}

// ---------------- scores: g_ij per position; accumulate into s3 (over w) and s4 (over h) ----
#define SMEM_SCORES ((NE*NC*TW + NC*NC)*4 + 32*32*8)
__global__ void __launch_bounds__(256) scores_kernel(const float* __restrict__ x){
    extern __shared__ float sm[];
    float* Xs = sm;                          // [NE*NC][TW]
    float* Ms = sm + NE*NC*TW;               // Mt [cp][c]
    u64*  Ysp = (u64*)(Ms + NC*NC);          // [32 c-pairs][TW]

    const int tid = threadIdx.x, lane = tid & 31, warp = tid >> 5;
    const int b = blockIdx.z, h = blockIdx.y, w0 = blockIdx.x * TW;

    for (int i = tid; i < NC*NC/4; i += 256)
        ((float4*)Ms)[i] = ((const float4*)d_Mt)[i];

    const float* xb = x + (size_t)b*NE*NC*HW + h*NW + w0;
    for (int i = tid; i < NE*NC*(TW/4); i += 256){
        int row = i >> 3, q = i & 7;
        ((float4*)Xs)[i] = *(const float4*)(xb + (size_t)row*HW + q*4);
    }
    __syncthreads();

    const int c0 = warp * 8;
    for (int j = 0; j < NE; j++){
        // y_j = M x_j : warp computes 8 channels (4 packed pairs) per lane(w)
        u64 y0=0, y1=0, y2=0, y3=0;
        const float* xj = Xs + j*NC*TW + lane;
        const float* mr = Ms + c0;
        #pragma unroll 8
        for (int cp = 0; cp < NC; cp++){
            float xv = xj[cp*TW];
            u64 xx = pack2(xv, xv);
            ulonglong2 ma = *(const ulonglong2*)(mr + (size_t)cp*NC);
            ulonglong2 mb = *(const ulonglong2*)(mr + (size_t)cp*NC + 4);
            fma2(y0, ma.x, xx); fma2(y1, ma.y, xx);
            fma2(y2, mb.x, xx); fma2(y3, mb.y, xx);
        }
        Ysp[(warp*4+0)*TW + lane] = y0;
        Ysp[(warp*4+1)*TW + lane] = y1;
        Ysp[(warp*4+2)*TW + lane] = y2;
        Ysp[(warp*4+3)*TW + lane] = y3;
        __syncthreads();

        // g_ij = x_i . y_j ; warp owns ensemble i = warp (+8), lane owns w
        for (int i = warp; i < NE; i += 8){
            u64 g2 = 0;
            const float* xi = Xs + i*NC*TW + lane;
            #pragma unroll 8
            for (int p = 0; p < 32; p++){
                u64 xp = pack2(xi[(2*p)*TW], xi[(2*p+1)*TW]);
                fma2(g2, xp, Ysp[p*TW + lane]);
            }
            float2 gf = unpack2(g2);
            float g = gf.x + gf.y;
            atomicAdd(&d_s4[((b*NW + w0 + lane)*NE + i)*NE + j], g);
            #pragma unroll
            for (int off = 16; off; off >>= 1) g += __shfl_down_sync(0xffffffffu, g, off);
            if (lane == 0) atomicAdd(&d_s3[((b*NH + h)*NE + i)*NE + j], g);
        }
        __syncthreads();
    }
}

// ---------------- softmax over j (in place), with the per-axis scale ----------------
__global__ void softmax_kernel(){
    int idx = blockIdx.x * blockDim.x + threadIdx.x;
    float* row; float scale;
    if (idx < NB*NH*NE){ row = d_s3 + idx*NE; scale = 1.0f/128.0f; }            // 1/sqrt(64*256)
    else {
        int r = idx - NB*NH*NE;
        if (r >= NB*NW*NE) return;
        row = d_s4 + r*NE; scale = rsqrtf(64.0f*128.0f);                         // 1/sqrt(64*128)
    }
    float v[NE], m = -3.4e38f;
    #pragma unroll
    for (int j = 0; j < NE; j++){ v[j] = row[j]*scale; m = fmaxf(m, v[j]); }
    float s = 0.f;
    #pragma unroll
    for (int j = 0; j < NE; j++){ v[j] = expf(v[j] - m); s += v[j]; }
    float inv = 1.0f/s;
    #pragma unroll
    for (int j = 0; j < NE; j++) row[j] = v[j]*inv;
}

// ---------------- output: z = sum_j (w3+w4)_ij x_j ; y = P z + 2x ; gelu ----------------
#define SMEM_OUT ((NE*NC*TW + NC*NC + NC*TW + NE*NE)*4)
__global__ void __launch_bounds__(256) output_kernel(const float* __restrict__ x,
                                                     float* __restrict__ out){
    extern __shared__ float sm[];
    float* Xs  = sm;                         // [NE*NC][TW]
    float* Ps  = sm + NE*NC*TW;              // Pt [c][d]
    float* Zs  = Ps + NC*NC;                 // [NC][TW]
    float* w3s = Zs + NC*TW;                 // [NE*NE]

    const int tid = threadIdx.x, lane = tid & 31, warp = tid >> 5;
    const int b = blockIdx.z, h = blockIdx.y, w0 = blockIdx.x * TW;

    for (int i = tid; i < NC*NC/4; i += 256)
        ((float4*)Ps)[i] = ((const float4*)d_Pt)[i];
    if (tid < NE*NE) w3s[tid] = d_s3[(b*NH + h)*NE*NE + tid];

    const float* xb = x + (size_t)b*NE*NC*HW + h*NW + w0;
    for (int i = tid; i < NE*NC*(TW/4); i += 256){
        int row = i >> 3, q = i & 7;
        ((float4*)Xs)[i] = *(const float4*)(xb + (size_t)row*HW + q*4);
    }
    __syncthreads();

    const float* w4p = d_s4 + (size_t)((b*NW + w0 + lane))*NE*NE;   // per-lane w row
    const int c0 = warp * 8;

    for (int i = 0; i < NE; i++){
        // z[c] = sum_j cw_j * x_j[c], warp computes channels c0..c0+7
        float z[8] = {0,0,0,0,0,0,0,0};
        #pragma unroll
        for (int j = 0; j < NE; j++){
            float cw = w3s[i*NE + j] + w4p[i*NE + j];
            const float* xj = Xs + j*NC*TW + c0*TW + lane;
            #pragma unroll
            for (int k = 0; k < 8; k++) z[k] = fmaf(cw, xj[k*TW], z[k]);
        }
        #pragma unroll
        for (int k = 0; k < 8; k++) Zs[(c0+k)*TW + lane] = z[k];
        __syncthreads();

        // y[d] = 2*x_i[d] + sum_c P[d][c] z[c], warp computes d0=c0..c0+7 (packed pairs)
        const float* xi = Xs + i*NC*TW + c0*TW + lane;
        u64 y0 = pack2(2.f*xi[0*TW], 2.f*xi[1*TW]);
        u64 y1 = pack2(2.f*xi[2*TW], 2.f*xi[3*TW]);
        u64 y2 = pack2(2.f*xi[4*TW], 2.f*xi[5*TW]);
        u64 y3 = pack2(2.f*xi[6*TW], 2.f*xi[7*TW]);
        const float* pr = Ps + c0;
        #pragma unroll 8
        for (int c = 0; c < NC; c++){
            float zv = Zs[c*TW + lane];
            u64 zz = pack2(zv, zv);
            ulonglong2 pa = *(const ulonglong2*)(pr + (size_t)c*NC);
            ulonglong2 pb = *(const ulonglong2*)(pr + (size_t)c*NC + 4);
            fma2(y0, pa.x, zz); fma2(y1, pa.y, zz);
            fma2(y2, pb.x, zz); fma2(y3, pb.y, zz);
        }
        float yv[8];
        { float2 t; t=unpack2(y0); yv[0]=t.x; yv[1]=t.y;
          t=unpack2(y1); yv[2]=t.x; yv[3]=t.y;
          t=unpack2(y2); yv[4]=t.x; yv[5]=t.y;
          t=unpack2(y3); yv[6]=t.x; yv[7]=t.y; }

        float* op = out + ((size_t)(b*NE + i)*NC + c0)*HW + h*NW + w0 + lane;
        #pragma unroll
        for (int k = 0; k < 8; k++){
            float t = yv[k];
            float g = 0.5f*t*(1.0f + tanhf(0.7978845608028654f*(t + 0.044715f*t*t*t)));
            op[(size_t)k*HW] = g;
        }
        __syncthreads();   // Zs reused next i
    }
}

// ---------------- launch ----------------
extern "C" void kernel_launch(void* const* d_in, const int* in_sizes, int n_in,
                              void* d_out, int out_size){
    const float* x  = (const float*)d_in[0];
    const float* Wv = (const float*)d_in[1];
    const float* Wk = (const float*)d_in[2];
    const float* Wq = (const float*)d_in[3];
    const float* Wo = (const float*)d_in[4];
    float* out = (float*)d_out;

    cudaFuncSetAttribute(scores_kernel, cudaFuncAttributeMaxDynamicSharedMemorySize, SMEM_SCORES);
    cudaFuncSetAttribute(output_kernel, cudaFuncAttributeMaxDynamicSharedMemorySize, SMEM_OUT);

    prep_kernel<<<(2*NC*NC + 255)/256, 256>>>(Wq, Wk, Wv, Wo);
    zero_kernel<<<(NB*NH*NE*NE + NB*NW*NE*NE + 255)/256, 256>>>();

    dim3 grid(NW/TW, NH, NB);
    scores_kernel<<<grid, 256, SMEM_SCORES>>>(x);
    softmax_kernel<<<(NB*NH*NE + NB*NW*NE + 255)/256, 256>>>();
    output_kernel<<<grid, 256, SMEM_OUT>>>(x, out);
}

// round 4
// speedup vs baseline: 1.3565x; 1.3565x over previous
#include <cuda_runtime.h>

#define NB 2
#define NE 10
#define NC 64
#define NH 128
#define NW 256
#define HW (NH*NW)
#define TW 32

// Persistent device scratch (no allocations allowed).
__device__ float d_Mt[NC*NC];          // Mt[cp*64+c] = M[c][cp] = sum_d Wq[d,c]*Wk[d,cp]
__device__ float d_Pt[NC*NC];          // Pt[c*64+d]  = P[d][c]  = sum_e Wo[d,e]*Wv[e,c]
__device__ float d_s3[NB*NH*NE*NE];    // axis=3 scores->weights [b][h][i][j]
__device__ float d_s4[NB*NW*NE*NE];    // axis=4 scores->weights [b][w][i][j]

typedef unsigned long long u64;

__device__ __forceinline__ u64 pack2(float lo, float hi){
    u64 r; asm("mov.b64 %0, {%1, %2};" : "=l"(r) : "f"(lo), "f"(hi)); return r;
}
__device__ __forceinline__ void fma2(u64 &d, u64 a, u64 b){
    asm("fma.rn.f32x2 %0, %1, %2, %0;" : "+l"(d) : "l"(a), "l"(b));
}
__device__ __forceinline__ float2 unpack2(u64 v){
    float2 r; asm("mov.b64 {%0, %1}, %2;" : "=f"(r.x), "=f"(r.y) : "l"(v)); return r;
}

// ---------------- prep: M = Wq^T Wk, P = Wo Wv (both stored transposed) ----------------
__global__ void prep_kernel(const float* __restrict__ Wq, const float* __restrict__ Wk,
                            const float* __restrict__ Wv, const float* __restrict__ Wo){
    int idx = blockIdx.x * blockDim.x + threadIdx.x;
    if (idx < NC*NC){
        int cp = idx >> 6, c = idx & 63;
        float s = 0.f;
        #pragma unroll 8
        for (int d = 0; d < NC; d++) s += Wq[d*NC + c] * Wk[d*NC + cp];
        d_Mt[idx] = s;                               // Mt[cp][c]
    } else if (idx < 2*NC*NC){
        int t = idx - NC*NC;
        int c = t >> 6, d = t & 63;
        float s = 0.f;
        #pragma unroll 8
        for (int e = 0; e < NC; e++) s += Wo[d*NC + e] * Wv[e*NC + c];
        d_Pt[t] = s;                                 // Pt[c][d]
    }
}

// ---------------- zero score accumulators ----------------
__global__ void zero_kernel(){
    int i = blockIdx.x * blockDim.x + threadIdx.x;
    if (i < NB*NH*NE*NE) d_s3[i] = 0.f;
    else {
        int r = i - NB*NH*NE*NE;
        if (r < NB*NW*NE*NE) d_s4[r] = 0.f;
    }
}

// ---------------- scores: g_ij per position; j processed in PAIRS ----------------
// smem: Xs [NE*NC][TW] | Ms [NC][NC] | Ysp u64 [64][TW]  (rows 0..31: j0, 32..63: j1)
#define SMEM_SCORES ((NE*NC*TW + NC*NC)*4 + 64*TW*8)
__global__ void __launch_bounds__(256) scores_kernel(const float* __restrict__ x){
    extern __shared__ float sm[];
    float* Xs = sm;
    float* Ms = sm + NE*NC*TW;
    u64*  Ysp = (u64*)(Ms + NC*NC);

    const int tid = threadIdx.x, lane = tid & 31, warp = tid >> 5;
    const int b = blockIdx.z, h = blockIdx.y, w0 = blockIdx.x * TW;

    for (int i = tid; i < NC*NC/4; i += 256)
        ((float4*)Ms)[i] = ((const float4*)d_Mt)[i];

    const float* xb = x + (size_t)b*NE*NC*HW + h*NW + w0;
    for (int i = tid; i < NE*NC*(TW/4); i += 256){
        int row = i >> 3, q = i & 7;
        ((float4*)Xs)[i] = *(const float4*)(xb + (size_t)row*HW + q*4);
    }
    __syncthreads();

    const int c0 = warp * 8;
    for (int jp = 0; jp < NE; jp += 2){
        // ---- y phase for j0=jp, j1=jp+1: M row loads amortized over both
        u64 a0=0,a1=0,a2=0,a3=0, b0=0,b1=0,b2=0,b3=0;
        const float* xj0 = Xs + (size_t)jp*NC*TW + lane;
        const float* xj1 = xj0 + NC*TW;
        const float* mr  = Ms + c0;
        #pragma unroll 8
        for (int cp = 0; cp < NC; cp++){
            float v0 = xj0[cp*TW], v1 = xj1[cp*TW];
            u64 xx0 = pack2(v0, v0), xx1 = pack2(v1, v1);
            ulonglong2 ma = *(const ulonglong2*)(mr + (size_t)cp*NC);
            ulonglong2 mb = *(const ulonglong2*)(mr + (size_t)cp*NC + 4);
            fma2(a0, ma.x, xx0); fma2(a1, ma.y, xx0);
            fma2(a2, mb.x, xx0); fma2(a3, mb.y, xx0);
            fma2(b0, ma.x, xx1); fma2(b1, ma.y, xx1);
            fma2(b2, mb.x, xx1); fma2(b3, mb.y, xx1);
        }
        Ysp[(warp*4+0)*TW + lane] = a0;
        Ysp[(warp*4+1)*TW + lane] = a1;
        Ysp[(warp*4+2)*TW + lane] = a2;
        Ysp[(warp*4+3)*TW + lane] = a3;
        Ysp[(32+warp*4+0)*TW + lane] = b0;
        Ysp[(32+warp*4+1)*TW + lane] = b1;
        Ysp[(32+warp*4+2)*TW + lane] = b2;
        Ysp[(32+warp*4+3)*TW + lane] = b3;
        __syncthreads();

        // ---- g phase: each x_i pack feeds BOTH j0 and j1
        for (int i = warp; i < NE; i += 8){
            u64 g0 = 0, g1 = 0;
            const float* xi = Xs + (size_t)i*NC*TW + lane;
            #pragma unroll 8
            for (int p = 0; p < 32; p++){
                u64 xp = pack2(xi[(2*p)*TW], xi[(2*p+1)*TW]);
                fma2(g0, xp, Ysp[p*TW + lane]);
                fma2(g1, xp, Ysp[(32+p)*TW + lane]);
            }
            float2 f0 = unpack2(g0), f1 = unpack2(g1);
            float s0 = f0.x + f0.y, s1 = f1.x + f1.y;
            float* s4p = &d_s4[((b*NW + w0 + lane)*NE + i)*NE + jp];
            atomicAdd(s4p,     s0);
            atomicAdd(s4p + 1, s1);
            #pragma unroll
            for (int off = 16; off; off >>= 1){
                s0 += __shfl_down_sync(0xffffffffu, s0, off);
                s1 += __shfl_down_sync(0xffffffffu, s1, off);
            }
            if (lane == 0){
                float* s3p = &d_s3[((b*NH + h)*NE + i)*NE + jp];
                atomicAdd(s3p,     s0);
                atomicAdd(s3p + 1, s1);
            }
        }
        __syncthreads();
    }
}

// ---------------- softmax over j (in place), with the per-axis scale ----------------
__global__ void softmax_kernel(){
    int idx = blockIdx.x * blockDim.x + threadIdx.x;
    float* row; float scale;
    if (idx < NB*NH*NE){ row = d_s3 + idx*NE; scale = 1.0f/128.0f; }            // 1/sqrt(64*256)
    else {
        int r = idx - NB*NH*NE;
        if (r >= NB*NW*NE) return;
        row = d_s4 + r*NE; scale = rsqrtf(64.0f*128.0f);                         // 1/sqrt(64*128)
    }
    float v[NE], m = -3.4e38f;
    #pragma unroll
    for (int j = 0; j < NE; j++){ v[j] = row[j]*scale; m = fmaxf(m, v[j]); }
    float s = 0.f;
    #pragma unroll
    for (int j = 0; j < NE; j++){ v[j] = expf(v[j] - m); s += v[j]; }
    float inv = 1.0f/s;
    #pragma unroll
    for (int j = 0; j < NE; j++) row[j] = v[j]*inv;
}

// ---------------- output: i processed in PAIRS; z = sum_j cw_j x_j ; y = P z + 2x ; gelu ----
// smem: Xs [NE*NC][TW] | Ps [NC][NC] | Zs [2*NC][TW] | w3s [NE*NE]
#define SMEM_OUT ((NE*NC*TW + NC*NC + 2*NC*TW + NE*NE)*4)
__global__ void __launch_bounds__(256) output_kernel(const float* __restrict__ x,
                                                     float* __restrict__ out){
    extern __shared__ float sm[];
    float* Xs  = sm;
    float* Ps  = sm + NE*NC*TW;
    float* Zs  = Ps + NC*NC;
    float* w3s = Zs + 2*NC*TW;

    const int tid = threadIdx.x, lane = tid & 31, warp = tid >> 5;
    const int b = blockIdx.z, h = blockIdx.y, w0 = blockIdx.x * TW;

    for (int i = tid; i < NC*NC/4; i += 256)
        ((float4*)Ps)[i] = ((const float4*)d_Pt)[i];
    if (tid < NE*NE) w3s[tid] = d_s3[(b*NH + h)*NE*NE + tid];

    const float* xb = x + (size_t)b*NE*NC*HW + h*NW + w0;
    for (int i = tid; i < NE*NC*(TW/4); i += 256){
        int row = i >> 3, q = i & 7;
        ((float4*)Xs)[i] = *(const float4*)(xb + (size_t)row*HW + q*4);
    }
    __syncthreads();

    const float* w4p = d_s4 + (size_t)(b*NW + w0 + lane)*NE*NE;   // per-lane w row
    const int c0 = warp * 8;

    for (int ip = 0; ip < NE; ip += 2){
        const int i0 = ip, i1 = ip + 1;
        // ---- z phase: channels c0..c0+7 for BOTH i0 and i1 (x_j loads shared)
        u64 z0[4] = {0,0,0,0}, z1[4] = {0,0,0,0};
        #pragma unroll
        for (int j = 0; j < NE; j++){
            float c_0 = w3s[i0*NE + j] + w4p[i0*NE + j];
            float c_1 = w3s[i1*NE + j] + w4p[i1*NE + j];
            u64 cw0 = pack2(c_0, c_0), cw1 = pack2(c_1, c_1);
            const float* xj = Xs + (size_t)j*NC*TW + c0*TW + lane;
            #pragma unroll
            for (int k = 0; k < 4; k++){
                u64 xv = pack2(xj[(2*k)*TW], xj[(2*k+1)*TW]);
                fma2(z0[k], xv, cw0);
                fma2(z1[k], xv, cw1);
            }
        }
        #pragma unroll
        for (int k = 0; k < 4; k++){
            float2 t0 = unpack2(z0[k]), t1 = unpack2(z1[k]);
            Zs[(c0 + 2*k    )*TW + lane] = t0.x;
            Zs[(c0 + 2*k + 1)*TW + lane] = t0.y;
            Zs[(NC*TW) + (c0 + 2*k    )*TW + lane - c0*0] = 0.f; // placeholder removed below
        }
        // store z1 into second half of Zs
        #pragma unroll
        for (int k = 0; k < 4; k++){
            float2 t1 = unpack2(z1[k]);
            Zs[NC*TW + (c0 + 2*k    )*TW + lane] = t1.x;
            Zs[NC*TW + (c0 + 2*k + 1)*TW + lane] = t1.y;
        }
        __syncthreads();

        // ---- y phase: d-channels c0..c0+7; P row loads amortized over i0,i1
        const float* xi0 = Xs + (size_t)i0*NC*TW + c0*TW + lane;
        const float* xi1 = Xs + (size_t)i1*NC*TW + c0*TW + lane;
        u64 ya0 = pack2(2.f*xi0[0*TW], 2.f*xi0[1*TW]);
        u64 ya1 = pack2(2.f*xi0[2*TW], 2.f*xi0[3*TW]);
        u64 ya2 = pack2(2.f*xi0[4*TW], 2.f*xi0[5*TW]);
        u64 ya3 = pack2(2.f*xi0[6*TW], 2.f*xi0[7*TW]);
        u64 yb0 = pack2(2.f*xi1[0*TW], 2.f*xi1[1*TW]);
        u64 yb1 = pack2(2.f*xi1[2*TW], 2.f*xi1[3*TW]);
        u64 yb2 = pack2(2.f*xi1[4*TW], 2.f*xi1[5*TW]);
        u64 yb3 = pack2(2.f*xi1[6*TW], 2.f*xi1[7*TW]);
        const float* pr = Ps + c0;
        #pragma unroll 8
        for (int c = 0; c < NC; c++){
            float zv0 = Zs[c*TW + lane];
            float zv1 = Zs[NC*TW + c*TW + lane];
            u64 zz0 = pack2(zv0, zv0), zz1 = pack2(zv1, zv1);
            ulonglong2 pa = *(const ulonglong2*)(pr + (size_t)c*NC);
            ulonglong2 pb = *(const ulonglong2*)(pr + (size_t)c*NC + 4);
            fma2(ya0, pa.x, zz0); fma2(ya1, pa.y, zz0);
            fma2(ya2, pb.x, zz0); fma2(ya3, pb.y, zz0);
            fma2(yb0, pa.x, zz1); fma2(yb1, pa.y, zz1);
            fma2(yb2, pb.x, zz1); fma2(yb3, pb.y, zz1);
        }
        float va[8], vb[8];
        { float2 t;
          t=unpack2(ya0); va[0]=t.x; va[1]=t.y;
          t=unpack2(ya1); va[2]=t.x; va[3]=t.y;
          t=unpack2(ya2); va[4]=t.x; va[5]=t.y;
          t=unpack2(ya3); va[6]=t.x; va[7]=t.y;
          t=unpack2(yb0); vb[0]=t.x; vb[1]=t.y;
          t=unpack2(yb1); vb[2]=t.x; vb[3]=t.y;
          t=unpack2(yb2); vb[4]=t.x; vb[5]=t.y;
          t=unpack2(yb3); vb[6]=t.x; vb[7]=t.y; }

        float* op0 = out + ((size_t)(b*NE + i0)*NC + c0)*HW + h*NW + w0 + lane;
        float* op1 = out + ((size_t)(b*NE + i1)*NC + c0)*HW + h*NW + w0 + lane;
        #pragma unroll
        for (int k = 0; k < 8; k++){
            float t0 = va[k], t1 = vb[k];
            float g0 = 0.5f*t0*(1.0f + tanhf(0.7978845608028654f*(t0 + 0.044715f*t0*t0*t0)));
            float g1 = 0.5f*t1*(1.0f + tanhf(0.7978845608028654f*(t1 + 0.044715f*t1*t1*t1)));
            op0[(size_t)k*HW] = g0;
            op1[(size_t)k*HW] = g1;
        }
        __syncthreads();   // Zs reused next pair
    }
}

// ---------------- launch ----------------
extern "C" void kernel_launch(void* const* d_in, const int* in_sizes, int n_in,
                              void* d_out, int out_size){
    const float* x  = (const float*)d_in[0];
    const float* Wv = (const float*)d_in[1];
    const float* Wk = (const float*)d_in[2];
    const float* Wq = (const float*)d_in[3];
    const float* Wo = (const float*)d_in[4];
    float* out = (float*)d_out;

    cudaFuncSetAttribute(scores_kernel, cudaFuncAttributeMaxDynamicSharedMemorySize, SMEM_SCORES);
    cudaFuncSetAttribute(output_kernel, cudaFuncAttributeMaxDynamicSharedMemorySize, SMEM_OUT);

    prep_kernel<<<(2*NC*NC + 255)/256, 256>>>(Wq, Wk, Wv, Wo);
    zero_kernel<<<(NB*NH*NE*NE + NB*NW*NE*NE + 255)/256, 256>>>();

    dim3 grid(NW/TW, NH, NB);
    scores_kernel<<<grid, 256, SMEM_SCORES>>>(x);
    softmax_kernel<<<(NB*NH*NE + NB*NW*NE + 255)/256, 256>>>();
    output_kernel<<<grid, 256, SMEM_OUT>>>(x, out);
}

// round 5
// speedup vs baseline: 1.4205x; 1.0471x over previous
#include <cuda_runtime.h>

#define NB 2
#define NE 10
#define NC 64
#define NH 128
#define NW 256
#define HW (NH*NW)
#define TW 16

// Persistent device scratch (no allocations allowed).
__device__ float d_Mt[NC*NC];          // Mt[cp*64+c] = M[c][cp] = sum_d Wq[d,c]*Wk[d,cp]
__device__ float d_Pt[NC*NC];          // Pt[c*64+d]  = P[d][c]  = sum_e Wo[d,e]*Wv[e,c]
__device__ float d_s3[NB*NH*NE*NE];    // axis=3 scores->weights [b][h][i][j]
__device__ float d_s4[NB*NW*NE*NE];    // axis=4 scores->weights [b][w][i][j]

typedef unsigned long long u64;

__device__ __forceinline__ u64 pack2(float lo, float hi){
    u64 r; asm("mov.b64 %0, {%1, %2};" : "=l"(r) : "f"(lo), "f"(hi)); return r;
}
__device__ __forceinline__ void fma2(u64 &d, u64 a, u64 b){
    asm("fma.rn.f32x2 %0, %1, %2, %0;" : "+l"(d) : "l"(a), "l"(b));
}
__device__ __forceinline__ float2 unpack2(u64 v){
    float2 r; asm("mov.b64 {%0, %1}, %2;" : "=f"(r.x), "=f"(r.y) : "l"(v)); return r;
}

// ---------------- prep: M = Wq^T Wk, P = Wo Wv (both stored transposed) ----------------
__global__ void prep_kernel(const float* __restrict__ Wq, const float* __restrict__ Wk,
                            const float* __restrict__ Wv, const float* __restrict__ Wo){
    int idx = blockIdx.x * blockDim.x + threadIdx.x;
    if (idx < NC*NC){
        int cp = idx >> 6, c = idx & 63;
        float s = 0.f;
        #pragma unroll 8
        for (int d = 0; d < NC; d++) s += Wq[d*NC + c] * Wk[d*NC + cp];
        d_Mt[idx] = s;                               // Mt[cp][c]
    } else if (idx < 2*NC*NC){
        int t = idx - NC*NC;
        int c = t >> 6, d = t & 63;
        float s = 0.f;
        #pragma unroll 8
        for (int e = 0; e < NC; e++) s += Wo[d*NC + e] * Wv[e*NC + c];
        d_Pt[t] = s;                                 // Pt[c][d]
    }
}

// ---------------- zero score accumulators ----------------
__global__ void zero_kernel(){
    int i = blockIdx.x * blockDim.x + threadIdx.x;
    if (i < NB*NH*NE*NE) d_s3[i] = 0.f;
    else {
        int r = i - NB*NH*NE*NE;
        if (r < NB*NW*NE*NE) d_s4[r] = 0.f;
    }
}

// ---------------- scores (TW=16): j in PAIRS; lane=(half,w) owns 4 channels x 1 w ----------
// smem: Xs [NE*NC][16] 40KB | Ms [64][64] 16KB | Ysp u64 [2][32 c-pairs][16] 8KB  => 64KB
#define SMEM_SCORES ((NE*NC*TW + NC*NC)*4 + 2*32*TW*8)
__global__ void __launch_bounds__(256, 3) scores_kernel(const float* __restrict__ x){
    extern __shared__ float sm[];
    float* Xs = sm;                         // row = e*64+c, idx = row*16 + w
    float* Ms = sm + NE*NC*TW;
    u64*  Ysp = (u64*)(Ms + NC*NC);         // [jj][p][w] : jj*512 + p*16 + w

    const int tid = threadIdx.x, lane = tid & 31, warp = tid >> 5;
    const int b = blockIdx.z, h = blockIdx.y, w0 = blockIdx.x * TW;
    const int wpos = lane & 15, half = lane >> 4;

    for (int i = tid; i < NC*NC/4; i += 256)
        ((float4*)Ms)[i] = ((const float4*)d_Mt)[i];

    const float* xb = x + (size_t)b*NE*NC*HW + h*NW + w0;
    for (int i = tid; i < NE*NC*(TW/4); i += 256){
        int row = i >> 2, q = i & 3;
        ((float4*)Xs)[i] = *(const float4*)(xb + (size_t)row*HW + q*4);
    }
    __syncthreads();

    const int cc = warp*8 + half*4;         // 4 channels per lane
    const int p0 = cc >> 1;                 // channel-pair index
    for (int jp = 0; jp < NE; jp += 2){
        // ---- y phase: y_{j0}, y_{j1} channels cc..cc+3 for this lane's w
        u64 a0=0, a1=0, b0=0, b1=0;
        const float* xj0 = Xs + (size_t)jp*NC*TW + wpos;
        const float* xj1 = xj0 + NC*TW;
        #pragma unroll 8
        for (int cp = 0; cp < NC; cp++){
            float v0 = xj0[cp*TW], v1 = xj1[cp*TW];
            u64 xx0 = pack2(v0, v0), xx1 = pack2(v1, v1);
            ulonglong2 mv = *(const ulonglong2*)(Ms + (size_t)cp*NC + cc);
            fma2(a0, mv.x, xx0); fma2(a1, mv.y, xx0);
            fma2(b0, mv.x, xx1); fma2(b1, mv.y, xx1);
        }
        Ysp[       p0   *TW + wpos] = a0;
        Ysp[      (p0+1)*TW + wpos] = a1;
        Ysp[512 +  p0   *TW + wpos] = b0;
        Ysp[512 + (p0+1)*TW + wpos] = b1;
        __syncthreads();

        // ---- g phase: thread=(i,w), 160 active threads (5 full warps)
        if (tid < NE*TW){
            const int gi = tid >> 4, gw = tid & 15;
            u64 g0 = 0, g1 = 0;
            const float* xi = Xs + (size_t)gi*NC*TW + gw;
            #pragma unroll 8
            for (int p = 0; p < 32; p++){
                u64 xp = pack2(xi[(2*p)*TW], xi[(2*p+1)*TW]);
                fma2(g0, xp, Ysp[p*TW + gw]);
                fma2(g1, xp, Ysp[512 + p*TW + gw]);
            }
            float2 f0 = unpack2(g0), f1 = unpack2(g1);
            float s0 = f0.x + f0.y, s1 = f1.x + f1.y;
            float* s4p = &d_s4[((b*NW + w0 + gw)*NE + gi)*NE + jp];
            atomicAdd(s4p,     s0);
            atomicAdd(s4p + 1, s1);
            #pragma unroll
            for (int off = 8; off; off >>= 1){
                s0 += __shfl_down_sync(0xffffffffu, s0, off, 16);
                s1 += __shfl_down_sync(0xffffffffu, s1, off, 16);
            }
            if (gw == 0){
                float* s3p = &d_s3[((b*NH + h)*NE + gi)*NE + jp];
                atomicAdd(s3p,     s0);
                atomicAdd(s3p + 1, s1);
            }
        }
        __syncthreads();
    }
}

// ---------------- softmax over j (in place), with the per-axis scale ----------------
__global__ void softmax_kernel(){
    int idx = blockIdx.x * blockDim.x + threadIdx.x;
    float* row; float scale;
    if (idx < NB*NH*NE){ row = d_s3 + idx*NE; scale = 1.0f/128.0f; }            // 1/sqrt(64*256)
    else {
        int r = idx - NB*NH*NE;
        if (r >= NB*NW*NE) return;
        row = d_s4 + r*NE; scale = rsqrtf(64.0f*128.0f);                         // 1/sqrt(64*128)
    }
    float v[NE], m = -3.4e38f;
    #pragma unroll
    for (int j = 0; j < NE; j++){ v[j] = row[j]*scale; m = fmaxf(m, v[j]); }
    float s = 0.f;
    #pragma unroll
    for (int j = 0; j < NE; j++){ v[j] = expf(v[j] - m); s += v[j]; }
    float inv = 1.0f/s;
    #pragma unroll
    for (int j = 0; j < NE; j++) row[j] = v[j]*inv;
}

// ---------------- output (TW=16): i in PAIRS; z then y=Pz+2x then gelu ----------------
// smem: Xs 40KB | Ps 16KB | Zs [2][64][16] 8KB | w3s 512B | w4s [16][100] 6.4KB => ~70.9KB
#define SMEM_OUT ((NE*NC*TW + NC*NC + 2*NC*TW + 128 + TW*NE*NE)*4)
__global__ void __launch_bounds__(256, 3) output_kernel(const float* __restrict__ x,
                                                        float* __restrict__ out){
    extern __shared__ float sm[];
    float* Xs  = sm;
    float* Ps  = sm + NE*NC*TW;
    float* Zs  = Ps + NC*NC;                 // [ii][c][w] : ii*NC*TW + c*TW + w
    float* w3s = Zs + 2*NC*TW;               // [NE*NE] (128 slots)
    float* w4s = w3s + 128;                  // [TW][NE*NE]

    const int tid = threadIdx.x, lane = tid & 31, warp = tid >> 5;
    const int b = blockIdx.z, h = blockIdx.y, w0 = blockIdx.x * TW;
    const int wpos = lane & 15, half = lane >> 4;

    for (int i = tid; i < NC*NC/4; i += 256)
        ((float4*)Ps)[i] = ((const float4*)d_Pt)[i];
    if (tid < NE*NE) w3s[tid] = d_s3[(b*NH + h)*NE*NE + tid];
    for (int t = tid; t < TW*NE*NE; t += 256)
        w4s[t] = d_s4[(size_t)(b*NW + w0)*NE*NE + t];      // rows w are contiguous

    const float* xb = x + (size_t)b*NE*NC*HW + h*NW + w0;
    for (int i = tid; i < NE*NC*(TW/4); i += 256){
        int row = i >> 2, q = i & 3;
        ((float4*)Xs)[i] = *(const float4*)(xb + (size_t)row*HW + q*4);
    }
    __syncthreads();

    const int cc = warp*8 + half*4;          // 4 channels per lane
    const float* w4r = w4s + wpos*NE*NE;

    for (int ip = 0; ip < NE; ip += 2){
        const int i0 = ip, i1 = ip + 1;
        // ---- z phase: z[cc..cc+3][wpos] for both i0,i1 (channel-pair packed)
        u64 z00=0, z01=0, z10=0, z11=0;
        #pragma unroll
        for (int j = 0; j < NE; j++){
            float c_0 = w3s[i0*NE + j] + w4r[i0*NE + j];
            float c_1 = w3s[i1*NE + j] + w4r[i1*NE + j];
            u64 cw0 = pack2(c_0, c_0), cw1 = pack2(c_1, c_1);
            const float* xj = Xs + (size_t)j*NC*TW + cc*TW + wpos;
            u64 xv0 = pack2(xj[0*TW], xj[1*TW]);
            u64 xv1 = pack2(xj[2*TW], xj[3*TW]);
            fma2(z00, xv0, cw0); fma2(z01, xv1, cw0);
            fma2(z10, xv0, cw1); fma2(z11, xv1, cw1);
        }
        { float2 t;
          t = unpack2(z00); Zs[(cc  )*TW + wpos] = t.x; Zs[(cc+1)*TW + wpos] = t.y;
          t = unpack2(z01); Zs[(cc+2)*TW + wpos] = t.x; Zs[(cc+3)*TW + wpos] = t.y;
          t = unpack2(z10); Zs[NC*TW + (cc  )*TW + wpos] = t.x; Zs[NC*TW + (cc+1)*TW + wpos] = t.y;
          t = unpack2(z11); Zs[NC*TW + (cc+2)*TW + wpos] = t.x; Zs[NC*TW + (cc+3)*TW + wpos] = t.y; }
        __syncthreads();

        // ---- y phase: y[d] = 2*x_i[d] + sum_c P[d][c] z[c], d = cc..cc+3
        const float* xi0 = Xs + (size_t)i0*NC*TW + cc*TW + wpos;
        const float* xi1 = Xs + (size_t)i1*NC*TW + cc*TW + wpos;
        u64 ya0 = pack2(2.f*xi0[0*TW], 2.f*xi0[1*TW]);
        u64 ya1 = pack2(2.f*xi0[2*TW], 2.f*xi0[3*TW]);
        u64 yb0 = pack2(2.f*xi1[0*TW], 2.f*xi1[1*TW]);
        u64 yb1 = pack2(2.f*xi1[2*TW], 2.f*xi1[3*TW]);
        #pragma unroll 8
        for (int c = 0; c < NC; c++){
            float zv0 = Zs[c*TW + wpos];
            float zv1 = Zs[NC*TW + c*TW + wpos];
            u64 zz0 = pack2(zv0, zv0), zz1 = pack2(zv1, zv1);
            ulonglong2 pv = *(const ulonglong2*)(Ps + (size_t)c*NC + cc);
            fma2(ya0, pv.x, zz0); fma2(ya1, pv.y, zz0);
            fma2(yb0, pv.x, zz1); fma2(yb1, pv.y, zz1);
        }
        float va[4], vb[4];
        { float2 t;
          t = unpack2(ya0); va[0]=t.x; va[1]=t.y;
          t = unpack2(ya1); va[2]=t.x; va[3]=t.y;
          t = unpack2(yb0); vb[0]=t.x; vb[1]=t.y;
          t = unpack2(yb1); vb[2]=t.x; vb[3]=t.y; }

        float* op0 = out + ((size_t)(b*NE + i0)*NC + cc)*HW + h*NW + w0 + wpos;
        float* op1 = out + ((size_t)(b*NE + i1)*NC + cc)*HW + h*NW + w0 + wpos;
        #pragma unroll
        for (int k = 0; k < 4; k++){
            float t0 = va[k], t1 = vb[k];
            float g0 = 0.5f*t0*(1.0f + tanhf(0.7978845608028654f*(t0 + 0.044715f*t0*t0*t0)));
            float g1 = 0.5f*t1*(1.0f + tanhf(0.7978845608028654f*(t1 + 0.044715f*t1*t1*t1)));
            op0[(size_t)k*HW] = g0;
            op1[(size_t)k*HW] = g1;
        }
        __syncthreads();   // Zs reused next pair
    }
}

// ---------------- launch ----------------
extern "C" void kernel_launch(void* const* d_in, const int* in_sizes, int n_in,
                              void* d_out, int out_size){
    const float* x  = (const float*)d_in[0];
    const float* Wv = (const float*)d_in[1];
    const float* Wk = (const float*)d_in[2];
    const float* Wq = (const float*)d_in[3];
    const float* Wo = (const float*)d_in[4];
    float* out = (float*)d_out;

    cudaFuncSetAttribute(scores_kernel, cudaFuncAttributeMaxDynamicSharedMemorySize, SMEM_SCORES);
    cudaFuncSetAttribute(output_kernel, cudaFuncAttributeMaxDynamicSharedMemorySize, SMEM_OUT);

    prep_kernel<<<(2*NC*NC + 255)/256, 256>>>(Wq, Wk, Wv, Wo);
    zero_kernel<<<(NB*NH*NE*NE + NB*NW*NE*NE + 255)/256, 256>>>();

    dim3 grid(NW/TW, NH, NB);
    scores_kernel<<<grid, 256, SMEM_SCORES>>>(x);
    softmax_kernel<<<(NB*NH*NE + NB*NW*NE + 255)/256, 256>>>();
    output_kernel<<<grid, 256, SMEM_OUT>>>(x, out);
}